// round 4
// baseline (speedup 1.0000x reference)
#include <cuda_runtime.h>
#include <cuda_bf16.h>
#include <cstdint>

// Problem: B=8, H=128, W=128, C=64, stride 2x2 max-unpool scatter-add.
// inputs  : [8,128,128,64] float32  -> 8,388,608 elements
// indices : [8,128,128,64] int32/int64 -> per-batch flat index into 256*256*64
// output  : [8,256,256,64] float32  -> 33,554,432 elements
static constexpr long long PER_BATCH_IN  = 128LL * 128 * 64;      // 2^20
static constexpr long long PER_BATCH_OUT = 256LL * 256 * 64;      // 2^22
static constexpr int NUM_BATCH = 8;

static constexpr int BLOCK   = 256;
static constexpr int GRID_P  = 148 * 4;   // 592 blocks, 4/SM -> guaranteed co-resident
static constexpr int NBPS    = 2;         // batches per pipeline phase
static constexpr int PHASES  = NUM_BATCH / NBPS + 1;  // 5: zero {2p,2p+1}, scatter {2p-2,2p-1}

// Runtime-detected layout flags + phase barrier counter.
__device__ int g_swap;   // 1 if d_in[0] is the indices buffer
__device__ int g_is64;   // 1 if indices are int64
__device__ unsigned int g_ctr;  // phase barrier arrival counter

// ---------------------------------------------------------------------------
// Probe: detect index buffer + width; reset the phase barrier counter.
// Indices are small non-negative ints (< 2^22); normal float bits viewed as
// int32 are ~1e9 or negative. int64 values < 2^22 have odd 32-bit words == 0.
// ---------------------------------------------------------------------------
__global__ void probe_kernel(const int* __restrict__ a, const int* __restrict__ b) {
    int k = threadIdx.x;                 // 0..255
    int va = a[k], vb = b[k];
    bool ok_a = (va >= 0 && va < (int)PER_BATCH_OUT);
    bool ok_b = (vb >= 0 && vb < (int)PER_BATCH_OUT);
    int ca = __syncthreads_count(ok_a);
    int cb = __syncthreads_count(ok_b);
    int swap = (ca > cb) ? 1 : 0;
    const int* idx = swap ? a : b;
    bool odd_nz = (idx[2 * k + 1] != 0);
    int nz = __syncthreads_count(odd_nz);
    if (k == 0) {
        g_swap = swap;
        g_is64 = (nz == 0) ? 1 : 0;
        g_ctr  = 0;                      // reset barrier for this replay
    }
}

// ---------------------------------------------------------------------------
// Persistent pipelined kernel. Phase p: zero batches [2p,2p+2), scatter
// batches [2p-2,2p). Global barrier between phases (counter + volatile spin).
// Keeping zero(b) one phase before scatter(b) makes each 32MB atomic RMW
// working set L2-resident: atomics hit dirty zero lines in L2, not DRAM.
// ---------------------------------------------------------------------------
__global__ void __launch_bounds__(BLOCK) unpool_persistent_kernel(
        const void* __restrict__ p0,
        const void* __restrict__ p1,
        float*      __restrict__ out) {

    const int swap = g_swap;
    const int is64 = g_is64;
    const float* in  = (const float*)(swap ? p1 : p0);
    const void*  idx = swap ? p0 : p1;

    const long long tid      = (long long)blockIdx.x * BLOCK + threadIdx.x;
    const long long nthreads = (long long)GRID_P * BLOCK;    // 151,552

    volatile unsigned int* ctr = &g_ctr;

    for (int p = 0; p < PHASES; p++) {
        // ---- zero part: batches [2p, 2p+2) — contiguous 8M floats = 2M float4
        if (p < PHASES - 1) {
            float4* dst = reinterpret_cast<float4*>(out + ((long long)(NBPS * p) << 22));
            const long long n4 = (NBPS * PER_BATCH_OUT) / 4;  // 2,097,152
            const float4 z = make_float4(0.f, 0.f, 0.f, 0.f);
            for (long long i = tid; i < n4; i += nthreads)
                dst[i] = z;
        }

        // ---- scatter part: batches [2p-2, 2p) — 2M elements = 512K groups of 4
        if (p > 0) {
            const long long g0 = ((long long)(NBPS * (p - 1)) << 20) >> 2;  // first group
            const long long ng = (NBPS * PER_BATCH_IN) / 4;                 // 524,288
            for (long long g = tid; g < ng; g += nthreads) {
                const long long tg = g0 + g;        // global 4-elem group id
                const long long i  = tg << 2;       // element index

                const float4 v = *reinterpret_cast<const float4*>(in + i);

                long long j0, j1, j2, j3;
                if (is64) {
                    const longlong2 a0 = reinterpret_cast<const longlong2*>(idx)[tg * 2 + 0];
                    const longlong2 a1 = reinterpret_cast<const longlong2*>(idx)[tg * 2 + 1];
                    j0 = a0.x; j1 = a0.y; j2 = a1.x; j3 = a1.y;
                } else {
                    const int4 a = reinterpret_cast<const int4*>(idx)[tg];
                    j0 = a.x; j1 = a.y; j2 = a.z; j3 = a.w;
                }

                float* ob = out + ((i >> 20) << 22);   // batch base
                if ((unsigned long long)j0 < (unsigned long long)PER_BATCH_OUT) atomicAdd(ob + j0, v.x);
                if ((unsigned long long)j1 < (unsigned long long)PER_BATCH_OUT) atomicAdd(ob + j1, v.y);
                if ((unsigned long long)j2 < (unsigned long long)PER_BATCH_OUT) atomicAdd(ob + j2, v.z);
                if ((unsigned long long)j3 < (unsigned long long)PER_BATCH_OUT) atomicAdd(ob + j3, v.w);
            }
        }

        // ---- global phase barrier (skip after last phase) ----
        if (p < PHASES - 1) {
            __syncthreads();
            if (threadIdx.x == 0) {
                __threadfence();
                atomicAdd(&g_ctr, 1u);
                const unsigned int target = (unsigned int)((p + 1) * GRID_P);
                while (*ctr < target)
                    __nanosleep(128);
            }
            __syncthreads();
            __threadfence();   // acquire: zeroed lines visible before atomics
        }
    }
}

extern "C" void kernel_launch(void* const* d_in, const int* in_sizes, int n_in,
                              void* d_out, int out_size) {
    const void* p0 = d_in[0];
    const void* p1 = d_in[1];
    float* out = (float*)d_out;

    probe_kernel<<<1, 256>>>((const int*)p0, (const int*)p1);
    unpool_persistent_kernel<<<GRID_P, BLOCK>>>(p0, p1, out);
}

// round 5
// speedup vs baseline: 1.2574x; 1.2574x over previous
#include <cuda_runtime.h>
#include <cuda_bf16.h>
#include <cstdint>

// Problem: B=8, H=128, W=128, C=64, stride 2x2 max-unpool scatter-add.
// inputs  : [8,128,128,64] float32  -> 8,388,608 elements
// indices : [8,128,128,64] int32/int64 -> per-batch flat index into 256*256*64
// output  : [8,256,256,64] float32  -> 33,554,432 elements
static constexpr long long PER_BATCH_IN  = 128LL * 128 * 64;      // 2^20
static constexpr long long PER_BATCH_OUT = 256LL * 256 * 64;      // 2^22
static constexpr int NUM_BATCH = 8;
static constexpr int NBPS      = 2;                    // batches per stage
static constexpr int NSTAGE    = NUM_BATCH / NBPS + 1; // 5

static constexpr int BLOCK = 256;
// Per stage: zero NBPS batches (2,097,152 float4) + scatter NBPS batches
// (2,097,152 elements). Block split inside one launch so they overlap.
static constexpr int ZBLK = 4096;   // 4096*256*2 float4 = 2,097,152
static constexpr int SBLK = 4096;   // 4096*256*2 elems  = 2,097,152
static constexpr int GRID = ZBLK + SBLK;

// Runtime-detected layout flags (set by the probe block in stage 0).
__device__ int g_swap;   // 1 if d_in[0] is the indices buffer
__device__ int g_is64;   // 1 if indices are int64

// ---------------------------------------------------------------------------
// Stage kernel. Stage s: zero batches [NBPS*s, NBPS*s+NBPS), scatter batches
// [NBPS*(s-1), NBPS*s). Launch boundaries order zero(b) before scatter(b), so
// each 32MB atomic RMW working set hits dirty zero lines resident in L2
// instead of doing DRAM read-modify-write.
// Stage 0 has no scatter; its last block runs the index-layout probe instead.
// ---------------------------------------------------------------------------
__global__ void __launch_bounds__(BLOCK) stage_kernel(
        const void* __restrict__ p0,
        const void* __restrict__ p1,
        float*      __restrict__ out,
        int stage) {

    if (blockIdx.x < ZBLK) {
        // ---- zero part: batches [NBPS*stage, NBPS*stage+NBPS) ----
        if (stage >= NSTAGE - 1) return;
        float4* dst = reinterpret_cast<float4*>(out + ((long long)(NBPS * stage) << 22));
        long long t = (long long)blockIdx.x * BLOCK + threadIdx.x;   // [0, 1,048,576)
        const long long stride = (long long)ZBLK * BLOCK;
        const float4 z = make_float4(0.f, 0.f, 0.f, 0.f);
        dst[t]          = z;
        dst[t + stride] = z;
        return;
    }

    if (stage == 0) {
        // ---- probe (one block): detect index buffer + width ----
        // Indices are small non-negative ints (< 2^22); normal float bits read
        // as int32 are ~1e9 or negative. int64 < 2^22 has odd words == 0.
        if (blockIdx.x != GRID - 1) return;
        const int* a = (const int*)p0;
        const int* b = (const int*)p1;
        int k = threadIdx.x;
        bool ok_a = (a[k] >= 0 && a[k] < (int)PER_BATCH_OUT);
        bool ok_b = (b[k] >= 0 && b[k] < (int)PER_BATCH_OUT);
        int ca = __syncthreads_count(ok_a);
        int cb = __syncthreads_count(ok_b);
        int swap = (ca > cb) ? 1 : 0;
        const int* idx = swap ? a : b;
        int nz = __syncthreads_count(idx[2 * k + 1] != 0);
        if (k == 0) { g_swap = swap; g_is64 = (nz == 0) ? 1 : 0; }
        return;
    }

    // ---- scatter part: batches [NBPS*(stage-1), NBPS*stage) ----
    const int swap = g_swap;
    const int is64 = g_is64;
    const float* in  = (const float*)(swap ? p1 : p0);
    const void*  idx = swap ? p0 : p1;

    const long long e0 = (long long)(NBPS * (stage - 1)) << 20;         // first element
    const long long t  = (long long)(blockIdx.x - ZBLK) * BLOCK + threadIdx.x;
    const long long i  = e0 + (t << 1);                                  // 2 elems/thread

    const float2 v = *reinterpret_cast<const float2*>(in + i);

    long long j0, j1;
    if (is64) {
        const longlong2 a = reinterpret_cast<const longlong2*>(idx)[i >> 1];
        j0 = a.x; j1 = a.y;
    } else {
        const int2 a = reinterpret_cast<const int2*>(idx)[i >> 1];
        j0 = a.x; j1 = a.y;
    }

    float* ob = out + ((i >> 20) << 22);   // batch base (both elems same batch)
    if ((unsigned long long)j0 < (unsigned long long)PER_BATCH_OUT) atomicAdd(ob + j0, v.x);
    if ((unsigned long long)j1 < (unsigned long long)PER_BATCH_OUT) atomicAdd(ob + j1, v.y);
}

extern "C" void kernel_launch(void* const* d_in, const int* in_sizes, int n_in,
                              void* d_out, int out_size) {
    const void* p0 = d_in[0];
    const void* p1 = d_in[1];
    float* out = (float*)d_out;

    // Stage 0: zero batches 0,1 + probe. Stages 1..4: zero next pair +
    // scatter previous pair. Stage 4: scatter only.
    for (int stage = 0; stage < NSTAGE; stage++) {
        stage_kernel<<<GRID, BLOCK>>>(p0, p1, out, stage);
    }
}

// round 6
// speedup vs baseline: 1.4543x; 1.1566x over previous
#include <cuda_runtime.h>
#include <cuda_bf16.h>
#include <cstdint>

// Problem: B=8, H=128, W=128, C=64, stride 2x2 max-unpool scatter-add.
// inputs  : [8,128,128,64] float32  -> 8,388,608 elements
// indices : [8,128,128,64] int32/int64 -> per-batch flat index into 256*256*64
// output  : [8,256,256,64] float32  -> 33,554,432 elements
static constexpr long long PER_BATCH_IN  = 128LL * 128 * 64;      // 2^20
static constexpr long long PER_BATCH_OUT = 256LL * 256 * 64;      // 2^22
static constexpr int NUM_BATCH = 8;
static constexpr int NSTAGE    = NUM_BATCH + 1;   // stage s: zero b=s, scatter b=s-1

static constexpr int BLOCK = 256;
// Per stage: zero 1 batch (1,048,576 float4 -> 2048 blocks x 2/thread),
// scatter 1 batch (1,048,576 elems -> 1024 blocks x 4/thread).
// Roles interleaved by blockIdx%3 so scatter starts immediately.
static constexpr int ZBLK = 2048;
static constexpr int SBLK = 1024;
static constexpr int GRID = ZBLK + SBLK;   // 3072

// Runtime-detected layout flags (set by the probe block in stage 0).
__device__ int g_swap;   // 1 if d_in[0] is the indices buffer
__device__ int g_is64;   // 1 if indices are int64

// ---------------------------------------------------------------------------
// Stage kernel. Stage s zeroes batch s while scattering batch s-1; the launch
// boundary orders zero(b) before scatter(b), so each 16MB atomic RMW working
// set hits dirty zero lines resident in L2 (no DRAM read-modify-write).
// Streaming reads use __ldcs (evict-first) to protect those L2 lines.
// ---------------------------------------------------------------------------
__global__ void __launch_bounds__(BLOCK) stage_kernel(
        const void* __restrict__ p0,
        const void* __restrict__ p1,
        float*      __restrict__ out,
        int stage) {

    const unsigned bx  = blockIdx.x;
    const unsigned rem = bx % 3u;
    const unsigned q   = bx / 3u;

    if (rem != 1u) {
        // ---- zero role (2048 blocks): batch = stage ----
        if (stage >= NUM_BATCH) return;
        const long long z = (long long)(q * 2 + (rem == 2u ? 1 : 0));   // [0,2048)
        float4* dst = reinterpret_cast<float4*>(out + ((long long)stage << 22));
        long long t = z * BLOCK + threadIdx.x;                          // [0, 524288)
        const float4 zz = make_float4(0.f, 0.f, 0.f, 0.f);
        dst[t]              = zz;
        dst[t + 524288LL]   = zz;
        return;
    }

    // ---- scatter role (1024 blocks): batch = stage - 1 ----
    const long long s = (long long)q;                                   // [0,1024)

    if (stage == 0) {
        // Probe (one block): detect which buffer is indices + their width.
        // Indices are small non-negative ints (< 2^22); normal float bits
        // read as int32 are ~1e9 or negative. int64 < 2^22 has odd words 0.
        if (s != 0) return;
        const int* a = (const int*)p0;
        const int* b = (const int*)p1;
        int k = threadIdx.x;
        bool ok_a = (a[k] >= 0 && a[k] < (int)PER_BATCH_OUT);
        bool ok_b = (b[k] >= 0 && b[k] < (int)PER_BATCH_OUT);
        int ca = __syncthreads_count(ok_a);
        int cb = __syncthreads_count(ok_b);
        int swap = (ca > cb) ? 1 : 0;
        const int* idx = swap ? a : b;
        int nz = __syncthreads_count(idx[2 * k + 1] != 0);
        if (k == 0) { g_swap = swap; g_is64 = (nz == 0) ? 1 : 0; }
        return;
    }

    const int swap = g_swap;
    const int is64 = g_is64;
    const float* in  = (const float*)(swap ? p1 : p0);
    const void*  idx = swap ? p0 : p1;

    const long long b  = stage - 1;
    const long long u  = s * BLOCK + threadIdx.x;            // [0, 262144)
    const long long tg = (b << 18) + u;                      // global 4-elem group
    const long long i  = tg << 2;                            // element index

    // Front-batched loads (MLP): value float4 + indices, all before atomics.
    const float4 v = __ldcs(reinterpret_cast<const float4*>(in + i));

    long long j0, j1, j2, j3;
    if (is64) {
        const longlong2 a0 = __ldcs(reinterpret_cast<const longlong2*>(idx) + tg * 2 + 0);
        const longlong2 a1 = __ldcs(reinterpret_cast<const longlong2*>(idx) + tg * 2 + 1);
        j0 = a0.x; j1 = a0.y; j2 = a1.x; j3 = a1.y;
    } else {
        const int4 a = __ldcs(reinterpret_cast<const int4*>(idx) + tg);
        j0 = a.x; j1 = a.y; j2 = a.z; j3 = a.w;
    }

    float* ob = out + (b << 22);   // batch base (all 4 elems same batch)
    if ((unsigned long long)j0 < (unsigned long long)PER_BATCH_OUT) atomicAdd(ob + j0, v.x);
    if ((unsigned long long)j1 < (unsigned long long)PER_BATCH_OUT) atomicAdd(ob + j1, v.y);
    if ((unsigned long long)j2 < (unsigned long long)PER_BATCH_OUT) atomicAdd(ob + j2, v.z);
    if ((unsigned long long)j3 < (unsigned long long)PER_BATCH_OUT) atomicAdd(ob + j3, v.w);
}

extern "C" void kernel_launch(void* const* d_in, const int* in_sizes, int n_in,
                              void* d_out, int out_size) {
    const void* p0 = d_in[0];
    const void* p1 = d_in[1];
    float* out = (float*)d_out;

    // Stage 0: zero batch 0 + probe. Stages 1..7: zero b + scatter b-1.
    // Stage 8: scatter batch 7 only.
    for (int stage = 0; stage < NSTAGE; stage++) {
        stage_kernel<<<GRID, BLOCK>>>(p0, p1, out, stage);
    }
}

// round 7
// speedup vs baseline: 1.4598x; 1.0038x over previous
#include <cuda_runtime.h>
#include <cuda_bf16.h>
#include <cstdint>

// Problem: B=8, H=128, W=128, C=64, stride 2x2 max-unpool scatter-add.
// inputs  : [8,128,128,64] float32  -> 8,388,608 elements
// indices : [8,128,128,64] int32/int64 -> per-batch flat index into 256*256*64
// output  : [8,256,256,64] float32  -> 33,554,432 elements
static constexpr long long PER_BATCH_OUT = 256LL * 256 * 64;      // 2^22
static constexpr int NUM_BATCH = 8;
static constexpr int NSTAGE    = NUM_BATCH + 1;   // stage s: zero b=s, scatter b=s-1

static constexpr int BLOCK = 256;
// Per stage: zero 1 batch (1,048,576 float4 -> 2048 blocks x 2/thread),
// scatter 1 batch (1,048,576 elems -> 1024 blocks x 4/thread).
// Roles interleaved by blockIdx%3.
static constexpr int ZBLK = 2048;
static constexpr int SBLK = 1024;
static constexpr int GRID = ZBLK + SBLK;   // 3072

// Runtime-detected layout flags (set by the probe block in stage 0).
__device__ int g_swap;   // 1 if d_in[0] is the indices buffer
__device__ int g_is64;   // 1 if indices are int64

// ---------------------------------------------------------------------------
// Stage kernel with PDL. Stage s zeroes batch s (independent -> pre-sync) and
// scatters batch s-1 (atomics require zero(s-1) from the previous grid ->
// post cudaGridDependencySynchronize). Zero(b) one launch before scatter(b)
// keeps each 16MB atomic RMW working set L2-resident (no DRAM RMW).
// ---------------------------------------------------------------------------
__global__ void __launch_bounds__(BLOCK) stage_kernel(
        const void* __restrict__ p0,
        const void* __restrict__ p1,
        float*      __restrict__ out,
        int stage) {

    // Let the next stage co-schedule immediately; its pre-sync work (zeroing,
    // value/index loads) overlaps our atomic drain.
    cudaTriggerProgrammaticLaunchCompletion();

    const unsigned bx  = blockIdx.x;
    const unsigned rem = bx % 3u;
    const unsigned q   = bx / 3u;

    if (rem != 1u) {
        // ---- zero role (2048 blocks): batch = stage. Fully independent. ----
        if (stage >= NUM_BATCH) return;
        const long long z = (long long)(q * 2 + (rem == 2u ? 1 : 0));   // [0,2048)
        float4* dst = reinterpret_cast<float4*>(out + ((long long)stage << 22));
        long long t = z * BLOCK + threadIdx.x;                          // [0, 524288)
        const float4 zz = make_float4(0.f, 0.f, 0.f, 0.f);
        dst[t]            = zz;
        dst[t + 524288LL] = zz;
        return;
    }

    // ---- scatter role (1024 blocks): batch = stage - 1 ----
    const long long s = (long long)q;                                   // [0,1024)

    if (stage == 0) {
        // Probe (one block): detect which buffer is indices + their width.
        // Indices are small non-negative ints (< 2^22); normal float bits
        // read as int32 are ~1e9 or negative. int64 < 2^22 has odd words 0.
        if (s != 0) return;
        const int* a = (const int*)p0;
        const int* b = (const int*)p1;
        int k = threadIdx.x;
        bool ok_a = (a[k] >= 0 && a[k] < (int)PER_BATCH_OUT);
        bool ok_b = (b[k] >= 0 && b[k] < (int)PER_BATCH_OUT);
        int ca = __syncthreads_count(ok_a);
        int cb = __syncthreads_count(ok_b);
        int swap = (ca > cb) ? 1 : 0;
        const int* idx = swap ? a : b;
        int nz = __syncthreads_count(idx[2 * k + 1] != 0);
        if (k == 0) { g_swap = swap; g_is64 = (nz == 0) ? 1 : 0; }
        return;
    }

    const long long b  = stage - 1;
    const long long u  = s * BLOCK + threadIdx.x;            // [0, 262144)
    const long long tg = (b << 18) + u;                      // global 4-elem group
    const long long i  = tg << 2;                            // element index

    // Speculative flag read (stable after stage 0; deterministic on replays).
    int swap_s = __ldcg(&g_swap);
    int is64_s = __ldcg(&g_is64);

    const float* in  = (const float*)(swap_s ? p1 : p0);
    const void*  idx = swap_s ? p0 : p1;

    // Front-batched loads (MLP), issued pre-sync so their DRAM latency hides
    // under the previous stage's atomic drain.
    float4 v = __ldcs(reinterpret_cast<const float4*>(in + i));
    long long j0, j1, j2, j3;
    if (is64_s) {
        const longlong2 a0 = __ldcs(reinterpret_cast<const longlong2*>(idx) + tg * 2 + 0);
        const longlong2 a1 = __ldcs(reinterpret_cast<const longlong2*>(idx) + tg * 2 + 1);
        j0 = a0.x; j1 = a0.y; j2 = a1.x; j3 = a1.y;
    } else {
        const int4 a = __ldcs(reinterpret_cast<const int4*>(idx) + tg);
        j0 = a.x; j1 = a.y; j2 = a.z; j3 = a.w;
    }

    // Wait for the previous grid (which zeroed batch b) to fully complete.
    cudaGridDependencySynchronize();

    // Re-check flags; if the speculation was wrong (possible only on the very
    // first execution while stage 0 was in flight), reload with correct ones.
    int swap_c = __ldcg(&g_swap);
    int is64_c = __ldcg(&g_is64);
    if (swap_c != swap_s || is64_c != is64_s) {
        const float* in2  = (const float*)(swap_c ? p1 : p0);
        const void*  idx2 = swap_c ? p0 : p1;
        v = __ldcs(reinterpret_cast<const float4*>(in2 + i));
        if (is64_c) {
            const longlong2 a0 = __ldcs(reinterpret_cast<const longlong2*>(idx2) + tg * 2 + 0);
            const longlong2 a1 = __ldcs(reinterpret_cast<const longlong2*>(idx2) + tg * 2 + 1);
            j0 = a0.x; j1 = a0.y; j2 = a1.x; j3 = a1.y;
        } else {
            const int4 a = __ldcs(reinterpret_cast<const int4*>(idx2) + tg);
            j0 = a.x; j1 = a.y; j2 = a.z; j3 = a.w;
        }
    }

    float* ob = out + (b << 22);   // batch base (all 4 elems same batch)
    if ((unsigned long long)j0 < (unsigned long long)PER_BATCH_OUT) atomicAdd(ob + j0, v.x);
    if ((unsigned long long)j1 < (unsigned long long)PER_BATCH_OUT) atomicAdd(ob + j1, v.y);
    if ((unsigned long long)j2 < (unsigned long long)PER_BATCH_OUT) atomicAdd(ob + j2, v.z);
    if ((unsigned long long)j3 < (unsigned long long)PER_BATCH_OUT) atomicAdd(ob + j3, v.w);
}

extern "C" void kernel_launch(void* const* d_in, const int* in_sizes, int n_in,
                              void* d_out, int out_size) {
    const void* p0 = d_in[0];
    const void* p1 = d_in[1];
    float* out = (float*)d_out;

    cudaLaunchAttribute attr[1];
    attr[0].id = cudaLaunchAttributeProgrammaticStreamSerialization;
    attr[0].val.programmaticStreamSerializationAllowed = 1;

    cudaLaunchConfig_t cfg = {};
    cfg.gridDim  = dim3(GRID, 1, 1);
    cfg.blockDim = dim3(BLOCK, 1, 1);
    cfg.dynamicSmemBytes = 0;
    cfg.stream = 0;              // legacy default stream (capture target)
    cfg.attrs = attr;
    cfg.numAttrs = 1;

    // Stage 0: zero batch 0 + probe. Stages 1..7: zero b + scatter b-1.
    // Stage 8: scatter batch 7 only. PDL overlaps adjacent stages.
    for (int stage = 0; stage < NSTAGE; stage++) {
        cudaLaunchKernelEx(&cfg, stage_kernel, p0, p1, out, stage);
    }
}

// round 8
// speedup vs baseline: 1.4709x; 1.0076x over previous
#include <cuda_runtime.h>
#include <cuda_bf16.h>
#include <cstdint>

// Problem: B=8, H=128, W=128, C=64, stride 2x2 max-unpool scatter-add.
// inputs  : [8,128,128,64] float32  -> 8,388,608 elements
// indices : [8,128,128,64] int32/int64 -> per-batch flat index into 256*256*64
// output  : [8,256,256,64] float32  -> 33,554,432 elements
static constexpr long long PER_BATCH_OUT = 256LL * 256 * 64;      // 2^22
static constexpr int NUM_BATCH = 8;
static constexpr int NSTAGE    = NUM_BATCH + 1;   // stage s: zero b=s, scatter b=s-1

static constexpr int BLOCK = 256;
static constexpr int GRID  = 1024;   // uniform blocks: each zeroes AND scatters
// Per stage, per thread: zero 4 float4 of batch s (1024*256*4 = 1,048,576 float4
// = 16MB) and scatter 4 elements of batch s-1 (1024*256*4 = 1,048,576 elems).

// Runtime-detected layout flags (set by the probe in stage 0).
__device__ int g_swap;   // 1 if d_in[0] is the indices buffer
__device__ int g_is64;   // 1 if indices are int64

// ---------------------------------------------------------------------------
// Stage kernel, uniform roles + PDL. Every block/thread does its zero slice
// (batch s, independent -> pre-sync) AND its scatter slice (batch s-1, loads
// pre-sync, atomics post-sync). Zero(b) one launch before scatter(b) keeps
// each 16MB atomic RMW working set L2-resident (no DRAM read-modify-write).
// All 7 LSU ops per thread are independent and front-issued for max MLP.
// ---------------------------------------------------------------------------
__global__ void __launch_bounds__(BLOCK) stage_kernel(
        const void* __restrict__ p0,
        const void* __restrict__ p1,
        float*      __restrict__ out,
        int stage) {

    cudaTriggerProgrammaticLaunchCompletion();

    const long long t = (long long)blockIdx.x * BLOCK + threadIdx.x;  // [0, 262144)

    // ---- scatter loads (batch s-1), issued FIRST: longest dependency chain.
    long long j0 = -1, j1 = -1, j2 = -1, j3 = -1;
    float4 v = make_float4(0.f, 0.f, 0.f, 0.f);
    int swap_s = 0, is64_s = 0;
    const long long b = (long long)stage - 1;
    if (stage > 0) {
        swap_s = __ldcg(&g_swap);
        is64_s = __ldcg(&g_is64);
        const float* in  = (const float*)(swap_s ? p1 : p0);
        const void*  idx = swap_s ? p0 : p1;
        const long long tg = (b << 18) + t;     // global 4-elem group id
        const long long i  = tg << 2;
        v = __ldcs(reinterpret_cast<const float4*>(in + i));
        if (is64_s) {
            const longlong2 a0 = __ldcs(reinterpret_cast<const longlong2*>(idx) + tg * 2 + 0);
            const longlong2 a1 = __ldcs(reinterpret_cast<const longlong2*>(idx) + tg * 2 + 1);
            j0 = a0.x; j1 = a0.y; j2 = a1.x; j3 = a1.y;
        } else {
            const int4 a = __ldcs(reinterpret_cast<const int4*>(idx) + tg);
            j0 = a.x; j1 = a.y; j2 = a.z; j3 = a.w;
        }
    }

    // ---- zero stores (batch s): independent, fire-and-forget.
    if (stage < NUM_BATCH) {
        float4* dst = reinterpret_cast<float4*>(out + ((long long)stage << 22));
        const float4 zz = make_float4(0.f, 0.f, 0.f, 0.f);
        #pragma unroll
        for (int r = 0; r < 4; r++)
            dst[t + (long long)r * 262144LL] = zz;
    }

    // ---- probe (stage 0, block 0): detect index buffer + width.
    // Indices are small non-negative ints (< 2^22); normal float bits read as
    // int32 are ~1e9 or negative. int64 < 2^22 has all odd 32-bit words == 0.
    if (stage == 0) {
        if (blockIdx.x == 0) {
            const int* a = (const int*)p0;
            const int* bb = (const int*)p1;
            int k = threadIdx.x;
            bool ok_a = (a[k]  >= 0 && a[k]  < (int)PER_BATCH_OUT);
            bool ok_b = (bb[k] >= 0 && bb[k] < (int)PER_BATCH_OUT);
            int ca = __syncthreads_count(ok_a);
            int cb = __syncthreads_count(ok_b);
            int swap = (ca > cb) ? 1 : 0;
            const int* idx = swap ? a : bb;
            int nz = __syncthreads_count(idx[2 * k + 1] != 0);
            if (k == 0) { g_swap = swap; g_is64 = (nz == 0) ? 1 : 0; }
        }
        return;
    }

    // ---- wait for previous grid (zero(b) + probe) to complete.
    cudaGridDependencySynchronize();

    // Re-check flags; reload if the speculation was wrong (at most once ever,
    // while stage 0's probe was still in flight; deterministic on replays).
    {
        int swap_c = __ldcg(&g_swap);
        int is64_c = __ldcg(&g_is64);
        if (swap_c != swap_s || is64_c != is64_s) {
            const float* in2  = (const float*)(swap_c ? p1 : p0);
            const void*  idx2 = swap_c ? p0 : p1;
            const long long tg = (b << 18) + t;
            const long long i  = tg << 2;
            v = __ldcs(reinterpret_cast<const float4*>(in2 + i));
            if (is64_c) {
                const longlong2 a0 = __ldcs(reinterpret_cast<const longlong2*>(idx2) + tg * 2 + 0);
                const longlong2 a1 = __ldcs(reinterpret_cast<const longlong2*>(idx2) + tg * 2 + 1);
                j0 = a0.x; j1 = a0.y; j2 = a1.x; j3 = a1.y;
            } else {
                const int4 a = __ldcs(reinterpret_cast<const int4*>(idx2) + tg);
                j0 = a.x; j1 = a.y; j2 = a.z; j3 = a.w;
            }
        }
    }

    // ---- scatter atomics (REDG; bounds-guarded).
    float* ob = out + (b << 22);
    if ((unsigned long long)j0 < (unsigned long long)PER_BATCH_OUT) atomicAdd(ob + j0, v.x);
    if ((unsigned long long)j1 < (unsigned long long)PER_BATCH_OUT) atomicAdd(ob + j1, v.y);
    if ((unsigned long long)j2 < (unsigned long long)PER_BATCH_OUT) atomicAdd(ob + j2, v.z);
    if ((unsigned long long)j3 < (unsigned long long)PER_BATCH_OUT) atomicAdd(ob + j3, v.w);
}

extern "C" void kernel_launch(void* const* d_in, const int* in_sizes, int n_in,
                              void* d_out, int out_size) {
    const void* p0 = d_in[0];
    const void* p1 = d_in[1];
    float* out = (float*)d_out;

    cudaLaunchAttribute attr[1];
    attr[0].id = cudaLaunchAttributeProgrammaticStreamSerialization;
    attr[0].val.programmaticStreamSerializationAllowed = 1;

    cudaLaunchConfig_t cfg = {};
    cfg.gridDim  = dim3(GRID, 1, 1);
    cfg.blockDim = dim3(BLOCK, 1, 1);
    cfg.dynamicSmemBytes = 0;
    cfg.stream = 0;
    cfg.attrs = attr;
    cfg.numAttrs = 1;

    // Stage 0: zero batch 0 + probe. Stages 1..7: zero b + scatter b-1.
    // Stage 8: scatter batch 7 only.
    for (int stage = 0; stage < NSTAGE; stage++) {
        cudaLaunchKernelEx(&cfg, stage_kernel, p0, p1, out, stage);
    }
}